// round 15
// baseline (speedup 1.0000x reference)
#include <cuda_runtime.h>

// Inverse 2D Haar DWT, collapsed to the per-2x2-block butterfly:
//   out[2i  ,2j  ] = 0.5*(LL + LH + HL + HH)
//   out[2i  ,2j+1] = 0.5*(LL - LH + HL - HH)
//   out[2i+1,2j  ] = 0.5*(LL + LH - HL - HH)
//   out[2i+1,2j+1] = 0.5*(LL - LH - HL + HH)
//
// Shapes: in (32,128,56,56) f32 x4 -> out (32,128,112,112) f32
//
// FINAL kernel — 14 rounds; converged and statistically validated
// (4 same-binary runs: ncu 56.8-58.2us, DRAM 77.7-79.7%, harness
// 63.68-63.97us — all variation is noise):
//  - math collapsed to a per-2x2 butterfly (no conv; reflect-pad hits the
//    zero-inserted row/col and vanishes) -> bytes at the 411MB minimum
//  - one input column-pair per thread; float2 streaming loads, perfectly
//    linear across the grid (in_off = 2*idx)
//  - two float4 streaming stores per thread, contiguous across the warp
//    per output row (512B/warp/instruction, no split sectors)
//  - exact grid, no tail predicate; single %28 for all index math
//  - 128-thread one-shot blocks (best-or-tied counters, occ 85-88%)
// Ruled out by measurement: persistent grid-stride (-7% DRAM), 64-thr
// blocks (-5%, 32-CTA/SM cap), STG.256 / float4 loads / vertical batching
// (neutral), paired float4 stores (-13%, sector splits).
// Steady state ~6.2-6.3 TB/s HBM = this chip's 4-read/1-write stream
// ceiling; all compute pipes <12%.

#define W_OUT  112
#define WPAIRS 28

__global__ __launch_bounds__(128)
void idwt_haar_kernel(const float* __restrict__ LL,
                      const float* __restrict__ LH,
                      const float* __restrict__ HL,
                      const float* __restrict__ HH,
                      float* __restrict__ out)
{
    unsigned idx = blockIdx.x * blockDim.x + threadIdx.x;   // exact grid, no tail

    unsigned jj      = idx % WPAIRS;
    long     in_off  = 2L * idx;
    long     out_off = 8L * idx - 4L * jj;

    float2 ll = __ldcs(reinterpret_cast<const float2*>(LL + in_off));
    float2 lh = __ldcs(reinterpret_cast<const float2*>(LH + in_off));
    float2 hl = __ldcs(reinterpret_cast<const float2*>(HL + in_off));
    float2 hh = __ldcs(reinterpret_cast<const float2*>(HH + in_off));

    float p0 = ll.x + hl.x, m0 = ll.x - hl.x;
    float q0 = lh.x + hh.x, r0 = lh.x - hh.x;
    float p1 = ll.y + hl.y, m1 = ll.y - hl.y;
    float q1 = lh.y + hh.y, r1 = lh.y - hh.y;

    float4 row_even = make_float4(0.5f * (p0 + q0), 0.5f * (p0 - q0),
                                  0.5f * (p1 + q1), 0.5f * (p1 - q1));
    float4 row_odd  = make_float4(0.5f * (m0 + r0), 0.5f * (m0 - r0),
                                  0.5f * (m1 + r1), 0.5f * (m1 - r1));

    __stcs(reinterpret_cast<float4*>(out + out_off),         row_even);
    __stcs(reinterpret_cast<float4*>(out + out_off + W_OUT), row_odd);
}

extern "C" void kernel_launch(void* const* d_in, const int* in_sizes, int n_in,
                              void* d_out, int out_size)
{
    const float* LL = (const float*)d_in[0];
    const float* LH = (const float*)d_in[1];
    const float* HL = (const float*)d_in[2];
    const float* HH = (const float*)d_in[3];
    float* out = (float*)d_out;

    int total   = in_sizes[0] / 2;          // 6,422,528 = 50176 * 128 exactly
    int threads = 128;
    int blocks  = total / threads;          // exact division, no remainder

    idwt_haar_kernel<<<blocks, threads>>>(LL, LH, HL, HH, out);
}

// round 16
// speedup vs baseline: 1.0055x; 1.0055x over previous
#include <cuda_runtime.h>

// Inverse 2D Haar DWT, collapsed to the per-2x2-block butterfly:
//   out[2i  ,2j  ] = 0.5*(LL + LH + HL + HH)
//   out[2i  ,2j+1] = 0.5*(LL - LH + HL - HH)
//   out[2i+1,2j  ] = 0.5*(LL + LH - HL - HH)
//   out[2i+1,2j+1] = 0.5*(LL - LH - HL + HH)
//
// Shapes: in (32,128,56,56) f32 x4 -> out (32,128,112,112) f32
//
// FINAL kernel — 15 rounds; converged and statistically validated
// (5 same-binary runs: ncu 56.8-58.2us, DRAM 77.7-79.7%, harness
// 63.68-64.00us — all residual variation is measurement noise):
//  - math collapsed to a per-2x2 butterfly (no conv; reflect-pad hits the
//    zero-inserted row/col and vanishes) -> bytes at the 411MB minimum
//  - one input column-pair per thread; float2 streaming loads, perfectly
//    linear across the grid (in_off = 2*idx)
//  - two float4 streaming stores per thread, contiguous across the warp
//    per output row (512B/warp/instruction, no split sectors)
//  - exact grid, no tail predicate; single %28 for all index math
//  - 128-thread one-shot blocks (best-or-tied counters, occ 84-88%)
// Ruled out by measurement: persistent grid-stride (-7% DRAM), 64-thr
// blocks (-5%, 32-CTA/SM cap), STG.256 / float4 loads / vertical batching
// (neutral), paired float4 stores (-13%, sector splits).
// Steady state ~6.2-6.3 TB/s HBM = this chip's 4-read/1-write stream
// ceiling; all compute pipes <12%. Converged.

#define W_OUT  112
#define WPAIRS 28

__global__ __launch_bounds__(128)
void idwt_haar_kernel(const float* __restrict__ LL,
                      const float* __restrict__ LH,
                      const float* __restrict__ HL,
                      const float* __restrict__ HH,
                      float* __restrict__ out)
{
    unsigned idx = blockIdx.x * blockDim.x + threadIdx.x;   // exact grid, no tail

    unsigned jj      = idx % WPAIRS;
    long     in_off  = 2L * idx;
    long     out_off = 8L * idx - 4L * jj;

    float2 ll = __ldcs(reinterpret_cast<const float2*>(LL + in_off));
    float2 lh = __ldcs(reinterpret_cast<const float2*>(LH + in_off));
    float2 hl = __ldcs(reinterpret_cast<const float2*>(HL + in_off));
    float2 hh = __ldcs(reinterpret_cast<const float2*>(HH + in_off));

    float p0 = ll.x + hl.x, m0 = ll.x - hl.x;
    float q0 = lh.x + hh.x, r0 = lh.x - hh.x;
    float p1 = ll.y + hl.y, m1 = ll.y - hl.y;
    float q1 = lh.y + hh.y, r1 = lh.y - hh.y;

    float4 row_even = make_float4(0.5f * (p0 + q0), 0.5f * (p0 - q0),
                                  0.5f * (p1 + q1), 0.5f * (p1 - q1));
    float4 row_odd  = make_float4(0.5f * (m0 + r0), 0.5f * (m0 - r0),
                                  0.5f * (m1 + r1), 0.5f * (m1 - r1));

    __stcs(reinterpret_cast<float4*>(out + out_off),         row_even);
    __stcs(reinterpret_cast<float4*>(out + out_off + W_OUT), row_odd);
}

extern "C" void kernel_launch(void* const* d_in, const int* in_sizes, int n_in,
                              void* d_out, int out_size)
{
    const float* LL = (const float*)d_in[0];
    const float* LH = (const float*)d_in[1];
    const float* HL = (const float*)d_in[2];
    const float* HH = (const float*)d_in[3];
    float* out = (float*)d_out;

    int total   = in_sizes[0] / 2;          // 6,422,528 = 50176 * 128 exactly
    int threads = 128;
    int blocks  = total / threads;          // exact division, no remainder

    idwt_haar_kernel<<<blocks, threads>>>(LL, LH, HL, HH, out);
}